// round 1
// baseline (speedup 1.0000x reference)
#include <cuda_runtime.h>
#include <cstdint>

// Problem constants (from reference): N=100000, E=3200000, B=512,
// F_X=64, F_U=128, F_OUT=128, K = F_X + F_U = 192.
#define MAXN   100000
#define FX     64
#define FU     128
#define FOUT   128

// Scratch: aggregated node features [N, FX]  (25.6 MB, static device global)
__device__ float g_agg[(size_t)MAXN * FX];
// dtype flags: [0] = edge_index is int64, [1] = batch is int64
__device__ int g_flags[2];

// ---------------------------------------------------------------------------
// vector reduction to global memory (sm_90+): 4 floats in one L2 atomic op
// ---------------------------------------------------------------------------
__device__ __forceinline__ void red_add_v4(float* addr, float4 v) {
    asm volatile("red.global.add.v4.f32 [%0], {%1,%2,%3,%4};"
                 :: "l"(addr), "f"(v.x), "f"(v.y), "f"(v.z), "f"(v.w)
                 : "memory");
}

// ---------------------------------------------------------------------------
// Kernel 0: detect whether edge_index / batch are int64 or int32.
// For int64 data with values in [0, N), every odd 32-bit word (the high half)
// is zero. For int32 data the sampled words are actual indices (nonzero whp).
// Sampling stays inside the first n_elems int32 words -> in-bounds either way.
// ---------------------------------------------------------------------------
__global__ void detect_kernel(const int* __restrict__ ei,
                              const int* __restrict__ batch,
                              int E, int N) {
    if (threadIdx.x != 0) return;
    // edge_index: sample odd words among the first 2*E int32 words
    int all0 = 1;
    for (int i = 0; i < 256; i++) {
        long long k = ((long long)i * 12497 + 1) % E;   // element index < E
        if (ei[2 * k + 1] != 0) { all0 = 0; break; }
    }
    g_flags[0] = all0;
    // batch: sorted 0..B-1; sample odd words with element index in
    // [N/4, N/2) so int32 values there are nonzero (bucket >= ~128).
    all0 = 1;
    int lo = N / 4, hi = N / 2;
    int step = (hi - lo) / 64; if (step < 1) step = 1;
    for (int i = 0; i < 64; i++) {
        long long k = lo + (long long)i * step;
        if (k >= hi) k = hi - 1;
        if (batch[2 * k + 1] != 0) { all0 = 0; break; }
    }
    g_flags[1] = all0;
}

// ---------------------------------------------------------------------------
// Kernel 1: zero the aggregation scratch (must be re-zeroed every call)
// ---------------------------------------------------------------------------
__global__ void zero_kernel(long n4) {
    long i = (long)blockIdx.x * blockDim.x + threadIdx.x;
    if (i < n4) ((float4*)g_agg)[i] = make_float4(0.f, 0.f, 0.f, 0.f);
}

// ---------------------------------------------------------------------------
// Kernel 2: scatter-add.  16 threads per edge, one float4 per thread.
//   agg[dest] += edge_attr[e] * x[src]
// ---------------------------------------------------------------------------
__global__ void scatter_kernel(const int* __restrict__ ei,
                               const float* __restrict__ eattr,
                               const float* __restrict__ x,
                               int E) {
    long long t = (long long)blockIdx.x * blockDim.x + threadIdx.x;
    long long e = t >> 4;
    int lane = (int)(t & 15);
    if (e >= E) return;

    int src, dst;
    if (g_flags[0]) {
        const long long* e64 = (const long long*)ei;
        src = (int)e64[e];
        dst = (int)e64[e + E];
    } else {
        src = ei[e];
        dst = ei[e + E];
    }
    float a = eattr[e];

    float4 v = ((const float4*)x)[(size_t)src * (FX / 4) + lane];
    v.x *= a; v.y *= a; v.z *= a; v.w *= a;

    red_add_v4(&g_agg[(size_t)dst * FX + lane * 4], v);
}

// ---------------------------------------------------------------------------
// Kernel 3: fused h = [agg | u[batch]];  out_half = h @ W_half + b_half.
// Tiled SGEMM: BM=128 rows x BN=128 cols, BK=16, 256 threads, 8x8 per thread.
// blockIdx.y selects K (0) or Q (1) half.
// ---------------------------------------------------------------------------
#define BM 128
#define BN 128
#define BK 16
#define TM 8
#define TN 8

__global__ __launch_bounds__(256)
void gemm_kernel(const float* __restrict__ u,
                 const int*   __restrict__ batch,
                 const float* __restrict__ WK, const float* __restrict__ bK,
                 const float* __restrict__ WQ, const float* __restrict__ bQ,
                 float* __restrict__ out, int N) {
    __shared__ float sh_h[BK][BM];   // [k][row]
    __shared__ float sh_w[BK][BN];   // [k][col]
    __shared__ int   sb[BM];

    const int tid  = threadIdx.x;
    const int row0 = blockIdx.x * BM;
    const int half = blockIdx.y;

    const float* W    = half ? WQ : WK;
    const float* bias = half ? bQ : bK;
    float* outbase    = out + (size_t)half * N * FOUT;

    const int b_is64 = g_flags[1];

    // batch indices for this row tile
    for (int i = tid; i < BM; i += 256) {
        int r = row0 + i;
        int b = 0;
        if (r < N)
            b = b_is64 ? (int)((const long long*)batch)[r] : batch[r];
        sb[i] = b;
    }
    __syncthreads();

    const int tx = tid & 15;   // col group: cols tx*8 .. tx*8+7
    const int ty = tid >> 4;   // row group: rows ty*8 .. ty*8+7

    float acc[TM][TN];
    #pragma unroll
    for (int i = 0; i < TM; i++)
        #pragma unroll
        for (int j = 0; j < TN; j++) acc[i][j] = 0.f;

    for (int kk = 0; kk < FX + FU; kk += BK) {
        // ---- load h tile: 128 rows x 16 k  (512 float4, 2 per thread) ----
        #pragma unroll
        for (int q = 0; q < 2; q++) {
            int f  = tid * 2 + q;        // float4 id in [0,512)
            int r  = f >> 2;             // row within tile
            int kq = (f & 3) * 4;        // k offset within chunk
            int gr = row0 + r;
            float4 v = make_float4(0.f, 0.f, 0.f, 0.f);
            if (gr < N) {
                int k = kk + kq;
                if (k < FX)
                    v = ((const float4*)g_agg)[(size_t)gr * (FX / 4) + (k >> 2)];
                else
                    v = ((const float4*)u)[(size_t)sb[r] * (FU / 4) + ((k - FX) >> 2)];
            }
            sh_h[kq + 0][r] = v.x;
            sh_h[kq + 1][r] = v.y;
            sh_h[kq + 2][r] = v.z;
            sh_h[kq + 3][r] = v.w;
        }
        // ---- load W tile: 16 k-rows x 128 cols (512 float4, 2 per thread) --
        #pragma unroll
        for (int q = 0; q < 2; q++) {
            int f  = tid * 2 + q;
            int kr = f >> 5;             // k-row within chunk (32 float4/row)
            int c4 = f & 31;
            float4 w = ((const float4*)(W + (size_t)(kk + kr) * FOUT))[c4];
            ((float4*)&sh_w[kr][0])[c4] = w;
        }
        __syncthreads();

        #pragma unroll
        for (int k = 0; k < BK; k++) {
            float a[TM], b[TN];
            #pragma unroll
            for (int i = 0; i < TM; i++) a[i] = sh_h[k][ty * TM + i];
            #pragma unroll
            for (int j = 0; j < TN; j++) b[j] = sh_w[k][tx * TN + j];
            #pragma unroll
            for (int i = 0; i < TM; i++)
                #pragma unroll
                for (int j = 0; j < TN; j++)
                    acc[i][j] = fmaf(a[i], b[j], acc[i][j]);
        }
        __syncthreads();
    }

    // ---- epilogue: add bias, store float4 ----
    float bb[TN];
    #pragma unroll
    for (int j = 0; j < TN; j++) bb[j] = bias[tx * TN + j];

    #pragma unroll
    for (int i = 0; i < TM; i++) {
        int r = row0 + ty * TM + i;
        if (r < N) {
            float4 o0 = make_float4(acc[i][0] + bb[0], acc[i][1] + bb[1],
                                    acc[i][2] + bb[2], acc[i][3] + bb[3]);
            float4 o1 = make_float4(acc[i][4] + bb[4], acc[i][5] + bb[5],
                                    acc[i][6] + bb[6], acc[i][7] + bb[7]);
            float4* dst = (float4*)(outbase + (size_t)r * FOUT + tx * TN);
            dst[0] = o0;
            dst[1] = o1;
        }
    }
}

// ---------------------------------------------------------------------------
// Launch
// ---------------------------------------------------------------------------
extern "C" void kernel_launch(void* const* d_in, const int* in_sizes, int n_in,
                              void* d_out, int out_size) {
    const float* x     = (const float*)d_in[0];
    const int*   ei    = (const int*)  d_in[1];
    const float* eattr = (const float*)d_in[2];
    const float* u     = (const float*)d_in[3];
    const int*   batch = (const int*)  d_in[4];
    const float* WK    = (const float*)d_in[5];
    const float* bK    = (const float*)d_in[6];
    const float* WQ    = (const float*)d_in[7];
    const float* bQ    = (const float*)d_in[8];
    float* out = (float*)d_out;

    const int E = in_sizes[2];           // edge_attr element count = E
    const int N = in_sizes[0] / FX;      // x element count / F_X

    detect_kernel<<<1, 32>>>(ei, batch, E, N);

    long n4 = (long)N * FX / 4;
    zero_kernel<<<(unsigned)((n4 + 255) / 256), 256>>>(n4);

    long long sthreads = (long long)E * 16;
    scatter_kernel<<<(unsigned)((sthreads + 255) / 256), 256>>>(ei, eattr, x, E);

    dim3 g((N + BM - 1) / BM, 2);
    gemm_kernel<<<g, 256>>>(u, batch, WK, bK, WQ, bQ, out, N);
}

// round 2
// speedup vs baseline: 1.4005x; 1.4005x over previous
#include <cuda_runtime.h>
#include <cstdint>

// Problem constants: N=100000, E=3200000, B=512, F_X=64, F_U=128, F_OUT=128.
#define MAXN   100000
#define MAXB   1024
#define FX     64
#define FU     128
#define FOUT   128

// Scratch: aggregated node features [N, FX] (25.6 MB)
__device__ float g_agg[(size_t)MAXN * FX];
// Scratch: per-batch precomputed u@W_bot + b for both halves: [B, 256]
__device__ float g_c[(size_t)MAXB * 256];
// dtype flags: [0] = edge_index is int64, [1] = batch is int64
__device__ int g_flags[2];

// ---------------------------------------------------------------------------
__device__ __forceinline__ void red_add_v4(float* addr, float4 v) {
    asm volatile("red.global.add.v4.f32 [%0], {%1,%2,%3,%4};"
                 :: "l"(addr), "f"(v.x), "f"(v.y), "f"(v.z), "f"(v.w)
                 : "memory");
}

// ---------------------------------------------------------------------------
// Kernel 0: parallel dtype detection (int64 vs int32) for edge_index / batch.
// int64 values < N have zero high words at odd 32-bit positions.
// ---------------------------------------------------------------------------
__global__ void detect_kernel(const int* __restrict__ ei,
                              const int* __restrict__ batch,
                              int E, int N) {
    __shared__ int s0, s1;
    if (threadIdx.x == 0) { s0 = 1; s1 = 1; }
    __syncthreads();
    int t = threadIdx.x;  // 256 threads
    long long k = ((long long)t * 12497 + 1) % E;
    if (ei[2 * k + 1] != 0) s0 = 0;          // benign race, same value
    if (t < 64) {
        int lo = N / 4, hi = N / 2;
        int step = (hi - lo) / 64; if (step < 1) step = 1;
        long long kb = lo + (long long)t * step;
        if (kb >= hi) kb = hi - 1;
        if (batch[2 * kb + 1] != 0) s1 = 0;
    }
    __syncthreads();
    if (threadIdx.x == 0) { g_flags[0] = s0; g_flags[1] = s1; }
}

// ---------------------------------------------------------------------------
// Kernel 1: zero the aggregation scratch
// ---------------------------------------------------------------------------
__global__ void zero_kernel(long n4) {
    long i = (long)blockIdx.x * blockDim.x + threadIdx.x;
    if (i < n4) ((float4*)g_agg)[i] = make_float4(0.f, 0.f, 0.f, 0.f);
}

// ---------------------------------------------------------------------------
// Kernel 2: scatter-add.  16 threads per edge, one float4 per thread.
// ---------------------------------------------------------------------------
__global__ void scatter_kernel(const int* __restrict__ ei,
                               const float* __restrict__ eattr,
                               const float* __restrict__ x,
                               int E) {
    long long t = (long long)blockIdx.x * blockDim.x + threadIdx.x;
    long long e = t >> 4;
    int lane = (int)(t & 15);
    if (e >= E) return;

    int src, dst;
    if (g_flags[0]) {
        const long long* e64 = (const long long*)ei;
        src = (int)e64[e];
        dst = (int)e64[e + E];
    } else {
        src = ei[e];
        dst = ei[e + E];
    }
    float a = eattr[e];

    float4 v = ((const float4*)x)[(size_t)src * (FX / 4) + lane];
    v.x *= a; v.y *= a; v.z *= a; v.w *= a;

    red_add_v4(&g_agg[(size_t)dst * FX + lane * 4], v);
}

// ---------------------------------------------------------------------------
// Kernel 3: tiny GEMM  g_c[b, half*128+j] = u[b,:] @ W_half[FX:,:][:,j] + b_half[j]
// grid (B, 2), 128 threads. 34 MFLOP total — latency-trivial.
// ---------------------------------------------------------------------------
__global__ void ugemm_kernel(const float* __restrict__ u,
                             const float* __restrict__ WK, const float* __restrict__ bK,
                             const float* __restrict__ WQ, const float* __restrict__ bQ) {
    int j    = threadIdx.x;        // 0..127
    int b    = blockIdx.x;
    int half = blockIdx.y;
    const float* W    = half ? WQ : WK;
    const float* bias = half ? bQ : bK;
    const float* urow = u + (size_t)b * FU;
    float acc = bias[j];
    #pragma unroll 8
    for (int k = 0; k < FU; k++)
        acc = fmaf(urow[k], W[(size_t)(FX + k) * FOUT + j], acc);
    g_c[(size_t)b * 256 + half * FOUT + j] = acc;
}

// ---------------------------------------------------------------------------
// Kernel 4: main GEMM with K=64:
//   out[half][n, j] = agg[n, 0:64] @ W_half[0:64, j] + g_c[batch[n], half*128+j]
// BM=128 x BN=128, BK=16 (4 iters), 256 threads, 8x8 per thread.
// ---------------------------------------------------------------------------
#define BM 128
#define BN 128
#define BK 16
#define TM 8
#define TN 8

__global__ __launch_bounds__(256)
void gemm_kernel(const int*   __restrict__ batch,
                 const float* __restrict__ WK,
                 const float* __restrict__ WQ,
                 float* __restrict__ out, int N) {
    __shared__ float sh_h[BK][BM];   // [k][row]
    __shared__ float sh_w[BK][BN];   // [k][col]
    __shared__ int   sb[BM];

    const int tid  = threadIdx.x;
    const int row0 = blockIdx.x * BM;
    const int half = blockIdx.y;

    const float* W = half ? WQ : WK;
    float* outbase = out + (size_t)half * N * FOUT;

    const int b_is64 = g_flags[1];

    for (int i = tid; i < BM; i += 256) {
        int r = row0 + i;
        int b = 0;
        if (r < N)
            b = b_is64 ? (int)((const long long*)batch)[r] : batch[r];
        sb[i] = b;
    }
    __syncthreads();

    const int tx = tid & 15;   // col group
    const int ty = tid >> 4;   // row group

    float acc[TM][TN];
    #pragma unroll
    for (int i = 0; i < TM; i++)
        #pragma unroll
        for (int j = 0; j < TN; j++) acc[i][j] = 0.f;

    #pragma unroll
    for (int kk = 0; kk < FX; kk += BK) {
        // h tile: 128 rows x 16 k (512 float4, 2 per thread), from g_agg only
        #pragma unroll
        for (int q = 0; q < 2; q++) {
            int f  = tid * 2 + q;
            int r  = f >> 2;
            int kq = (f & 3) * 4;
            int gr = row0 + r;
            float4 v = make_float4(0.f, 0.f, 0.f, 0.f);
            if (gr < N)
                v = ((const float4*)g_agg)[(size_t)gr * (FX / 4) + ((kk + kq) >> 2)];
            sh_h[kq + 0][r] = v.x;
            sh_h[kq + 1][r] = v.y;
            sh_h[kq + 2][r] = v.z;
            sh_h[kq + 3][r] = v.w;
        }
        // W tile: 16 k-rows x 128 cols
        #pragma unroll
        for (int q = 0; q < 2; q++) {
            int f  = tid * 2 + q;
            int kr = f >> 5;
            int c4 = f & 31;
            float4 w = ((const float4*)(W + (size_t)(kk + kr) * FOUT))[c4];
            ((float4*)&sh_w[kr][0])[c4] = w;
        }
        __syncthreads();

        #pragma unroll
        for (int k = 0; k < BK; k++) {
            float a[TM], b[TN];
            #pragma unroll
            for (int i = 0; i < TM; i++) a[i] = sh_h[k][ty * TM + i];
            #pragma unroll
            for (int j = 0; j < TN; j++) b[j] = sh_w[k][tx * TN + j];
            #pragma unroll
            for (int i = 0; i < TM; i++)
                #pragma unroll
                for (int j = 0; j < TN; j++)
                    acc[i][j] = fmaf(a[i], b[j], acc[i][j]);
        }
        __syncthreads();
    }

    // epilogue: add per-batch precomputed term, store
    #pragma unroll
    for (int i = 0; i < TM; i++) {
        int r = row0 + ty * TM + i;
        if (r < N) {
            const float* crow = &g_c[(size_t)sb[ty * TM + i] * 256 + half * FOUT + tx * TN];
            float4 c0 = ((const float4*)crow)[0];
            float4 c1 = ((const float4*)crow)[1];
            float4 o0 = make_float4(acc[i][0] + c0.x, acc[i][1] + c0.y,
                                    acc[i][2] + c0.z, acc[i][3] + c0.w);
            float4 o1 = make_float4(acc[i][4] + c1.x, acc[i][5] + c1.y,
                                    acc[i][6] + c1.z, acc[i][7] + c1.w);
            float4* dst = (float4*)(outbase + (size_t)r * FOUT + tx * TN);
            dst[0] = o0;
            dst[1] = o1;
        }
    }
}

// ---------------------------------------------------------------------------
extern "C" void kernel_launch(void* const* d_in, const int* in_sizes, int n_in,
                              void* d_out, int out_size) {
    const float* x     = (const float*)d_in[0];
    const int*   ei    = (const int*)  d_in[1];
    const float* eattr = (const float*)d_in[2];
    const float* u     = (const float*)d_in[3];
    const int*   batch = (const int*)  d_in[4];
    const float* WK    = (const float*)d_in[5];
    const float* bK    = (const float*)d_in[6];
    const float* WQ    = (const float*)d_in[7];
    const float* bQ    = (const float*)d_in[8];
    float* out = (float*)d_out;

    const int E = in_sizes[2];           // edge_attr element count = E
    const int N = in_sizes[0] / FX;      // x element count / F_X
    const int B = in_sizes[3] / FU;      // u element count / F_U

    detect_kernel<<<1, 256>>>(ei, batch, E, N);

    long n4 = (long)N * FX / 4;
    zero_kernel<<<(unsigned)((n4 + 255) / 256), 256>>>(n4);

    long long sthreads = (long long)E * 16;
    scatter_kernel<<<(unsigned)((sthreads + 255) / 256), 256>>>(ei, eattr, x, E);

    dim3 gu(B, 2);
    ugemm_kernel<<<gu, 128>>>(u, WK, bK, WQ, bQ);

    dim3 g((N + BM - 1) / BM, 2);
    gemm_kernel<<<g, 256>>>(batch, WK, WQ, out, N);
}

// round 4
// speedup vs baseline: 1.6769x; 1.1974x over previous
#include <cuda_runtime.h>
#include <cstdint>

// Problem constants: N=100000, E=3200000, B=512, F_X=64, F_U=128, F_OUT=128.
#define MAXN   100000
#define MAXB   1024
#define FX     64
#define FU     128
#define FOUT   128

__device__ float g_agg[(size_t)MAXN * FX];   // aggregated node feats [N, FX]
__device__ float g_c[(size_t)MAXB * 256];    // per-batch u@W_bot + b, both halves
__device__ int g_flags[2];                   // [0]=edge_index int64, [1]=batch int64

// ---------------------------------------------------------------------------
__device__ __forceinline__ void red_add_v4(float* addr, float4 v) {
    asm volatile("red.global.add.v4.f32 [%0], {%1,%2,%3,%4};"
                 :: "l"(addr), "f"(v.x), "f"(v.y), "f"(v.z), "f"(v.w)
                 : "memory");
}

__device__ __forceinline__ uint32_t f2tf32(float f) {
    uint32_t r;
    asm("cvt.rna.tf32.f32 %0, %1;" : "=r"(r) : "f"(f));
    return r;
}

// D += A(16x8) @ B(8x8), tf32 inputs, fp32 accumulate
__device__ __forceinline__ void mma_tf32(float* c, const uint32_t* a,
                                         const uint32_t* b) {
    asm volatile(
        "mma.sync.aligned.m16n8k8.row.col.f32.tf32.tf32.f32 "
        "{%0,%1,%2,%3}, {%4,%5,%6,%7}, {%8,%9}, {%0,%1,%2,%3};"
        : "+f"(c[0]), "+f"(c[1]), "+f"(c[2]), "+f"(c[3])
        : "r"(a[0]), "r"(a[1]), "r"(a[2]), "r"(a[3]), "r"(b[0]), "r"(b[1]));
}

// ---------------------------------------------------------------------------
// Kernel 0: dtype detection (int64 vs int32)
// ---------------------------------------------------------------------------
__global__ void detect_kernel(const int* __restrict__ ei,
                              const int* __restrict__ batch,
                              int E, int N) {
    __shared__ int s0, s1;
    if (threadIdx.x == 0) { s0 = 1; s1 = 1; }
    __syncthreads();
    int t = threadIdx.x;
    long long k = ((long long)t * 12497 + 1) % E;
    if (ei[2 * k + 1] != 0) s0 = 0;
    if (t < 64) {
        int lo = N / 4, hi = N / 2;
        int step = (hi - lo) / 64; if (step < 1) step = 1;
        long long kb = lo + (long long)t * step;
        if (kb >= hi) kb = hi - 1;
        if (batch[2 * kb + 1] != 0) s1 = 0;
    }
    __syncthreads();
    if (threadIdx.x == 0) { g_flags[0] = s0; g_flags[1] = s1; }
}

// ---------------------------------------------------------------------------
// Kernel 1: zero aggregation scratch
// ---------------------------------------------------------------------------
__global__ void zero_kernel(long n4) {
    long i = (long)blockIdx.x * blockDim.x + threadIdx.x;
    if (i < n4) ((float4*)g_agg)[i] = make_float4(0.f, 0.f, 0.f, 0.f);
}

// ---------------------------------------------------------------------------
// Kernel 2: scatter-add. 16 threads/edge, float4 reds.
// ---------------------------------------------------------------------------
__global__ void scatter_kernel(const int* __restrict__ ei,
                               const float* __restrict__ eattr,
                               const float* __restrict__ x,
                               int E) {
    long long t = (long long)blockIdx.x * blockDim.x + threadIdx.x;
    long long e = t >> 4;
    int lane = (int)(t & 15);
    if (e >= E) return;

    int src, dst;
    if (g_flags[0]) {
        const long long* e64 = (const long long*)ei;
        src = (int)e64[e];
        dst = (int)e64[e + E];
    } else {
        src = ei[e];
        dst = ei[e + E];
    }
    float a = eattr[e];

    float4 v = ((const float4*)x)[(size_t)src * (FX / 4) + lane];
    v.x *= a; v.y *= a; v.z *= a; v.w *= a;
    red_add_v4(&g_agg[(size_t)dst * FX + lane * 4], v);
}

// ---------------------------------------------------------------------------
// Kernel 3: u-term GEMM (exact fp32), 8 batch rows per block, u in smem.
//   g_c[b, half*128+j] = u[b,:] @ W_half[FX:,:][:,j] + bias_half[j]
// ---------------------------------------------------------------------------
__global__ __launch_bounds__(128)
void ugemm_kernel(const float* __restrict__ u,
                  const float* __restrict__ WK, const float* __restrict__ bK,
                  const float* __restrict__ WQ, const float* __restrict__ bQ,
                  int B) {
    __shared__ float su[8][FU];
    const int j    = threadIdx.x;      // 0..127
    const int half = blockIdx.y;
    const int b0   = blockIdx.x * 8;
    const float* W    = half ? WQ : WK;
    const float* bias = half ? bQ : bK;

    for (int f = j; f < 8 * FU; f += 128) {
        int i = f >> 7, k = f & 127;
        su[i][k] = (b0 + i < B) ? u[(size_t)(b0 + i) * FU + k] : 0.f;
    }
    __syncthreads();

    float acc[8];
    float bj = bias[j];
    #pragma unroll
    for (int i = 0; i < 8; i++) acc[i] = bj;

    #pragma unroll 4
    for (int k = 0; k < FU; k++) {
        float w = W[(size_t)(FX + k) * FOUT + j];
        #pragma unroll
        for (int i = 0; i < 8; i++)
            acc[i] = fmaf(su[i][k], w, acc[i]);
    }
    #pragma unroll
    for (int i = 0; i < 8; i++)
        if (b0 + i < B)
            g_c[(size_t)(b0 + i) * 256 + half * FOUT + j] = acc[i];
}

// ---------------------------------------------------------------------------
// Kernel 4: tf32 mma.sync GEMM.
//   out[half][m, n] = agg[m, 0:64] @ W_half[0:64, n] + g_c[batch[m], half, n]
// CTA tile 128x128, K=64. 8 warps (4 m x 2 n), warp tile 32x64.
// Smem: A_s[128][68] tf32-bits, B_s[128][68] tf32-bits (B_s[n][k] = W[k][n]).
// ---------------------------------------------------------------------------
#define ASTRIDE 68
#define SMEM_A_FLOATS (128 * ASTRIDE)
#define GEMM_SMEM_BYTES (2 * SMEM_A_FLOATS * 4 + 512)

__global__ __launch_bounds__(256)
void gemm_tc_kernel(const int*   __restrict__ batch,
                    const float* __restrict__ WK,
                    const float* __restrict__ WQ,
                    float* __restrict__ out, int N) {
    extern __shared__ uint32_t sm[];
    uint32_t* A_s = sm;                        // [128][68]
    uint32_t* B_s = sm + SMEM_A_FLOATS;        // [128][68]
    int* sb = (int*)(sm + 2 * SMEM_A_FLOATS);  // [128]

    const int tid  = threadIdx.x;
    const int wid  = tid >> 5;
    const int lane = tid & 31;
    const int grp  = lane >> 2;   // 0..7
    const int tig  = lane & 3;    // 0..3
    const int wm   = wid & 3;     // m-warp 0..3
    const int wn   = wid >> 2;    // n-warp 0..1
    const int row0 = blockIdx.x * 128;
    const int half = blockIdx.y;

    const float* W = half ? WQ : WK;
    float* outbase = out + (size_t)half * N * FOUT;

    // ---- stage batch indices ----
    const int b_is64 = g_flags[1];
    if (tid < 128) {
        int gr = row0 + tid;
        int b = 0;
        if (gr < N)
            b = b_is64 ? (int)((const long long*)batch)[gr] : batch[gr];
        sb[tid] = b;
    }

    // ---- stage A = agg tile [128 x 64] as tf32 bits ----
    #pragma unroll
    for (int it = 0; it < 8; it++) {
        int f  = it * 256 + tid;     // float4 id in [0,2048)
        int r  = f >> 4;
        int q  = f & 15;
        int gr = row0 + r;
        float4 v = make_float4(0.f, 0.f, 0.f, 0.f);
        if (gr < N) v = ((const float4*)g_agg)[(size_t)gr * 16 + q];
        uint4 w;
        w.x = f2tf32(v.x); w.y = f2tf32(v.y);
        w.z = f2tf32(v.z); w.w = f2tf32(v.w);
        *(uint4*)(A_s + r * ASTRIDE + q * 4) = w;
    }

    // ---- stage B_s[n][k] = W[k][n] as tf32 bits ----
    #pragma unroll
    for (int it = 0; it < 32; it++) {
        int f = it * 256 + tid;      // element id in [0,8192)
        int k = f >> 7;
        int n = f & 127;
        B_s[n * ASTRIDE + k] = f2tf32(W[(size_t)k * FOUT + n]);
    }
    __syncthreads();

    // ---- mma mainloop: 8 k-steps of 8 ----
    float acc[2][8][4];
    #pragma unroll
    for (int mi = 0; mi < 2; mi++)
        #pragma unroll
        for (int ni = 0; ni < 8; ni++)
            #pragma unroll
            for (int q = 0; q < 4; q++) acc[mi][ni][q] = 0.f;

    #pragma unroll
    for (int ks = 0; ks < 8; ks++) {
        const int k0 = ks * 8;
        uint32_t a[2][4];
        #pragma unroll
        for (int mi = 0; mi < 2; mi++) {
            int r = wm * 32 + mi * 16 + grp;
            a[mi][0] = A_s[(r    ) * ASTRIDE + k0 + tig    ];
            a[mi][1] = A_s[(r + 8) * ASTRIDE + k0 + tig    ];
            a[mi][2] = A_s[(r    ) * ASTRIDE + k0 + tig + 4];
            a[mi][3] = A_s[(r + 8) * ASTRIDE + k0 + tig + 4];
        }
        uint32_t b[8][2];
        #pragma unroll
        for (int ni = 0; ni < 8; ni++) {
            int n = wn * 64 + ni * 8 + grp;
            b[ni][0] = B_s[n * ASTRIDE + k0 + tig    ];
            b[ni][1] = B_s[n * ASTRIDE + k0 + tig + 4];
        }
        #pragma unroll
        for (int mi = 0; mi < 2; mi++)
            #pragma unroll
            for (int ni = 0; ni < 8; ni++)
                mma_tf32(acc[mi][ni], a[mi], b[ni]);
    }

    // ---- epilogue: add g_c[batch], store float2 pairs ----
    #pragma unroll
    for (int mi = 0; mi < 2; mi++) {
        #pragma unroll
        for (int rr = 0; rr < 2; rr++) {
            int r  = wm * 32 + mi * 16 + grp + rr * 8;
            int gr = row0 + r;
            if (gr < N) {
                const float* crow = &g_c[(size_t)sb[r] * 256 + half * FOUT];
                float* orow = outbase + (size_t)gr * FOUT;
                #pragma unroll
                for (int ni = 0; ni < 8; ni++) {
                    int col = wn * 64 + ni * 8 + tig * 2;
                    float2 c = *(const float2*)(crow + col);
                    float2 o;
                    o.x = acc[mi][ni][rr * 2 + 0] + c.x;
                    o.y = acc[mi][ni][rr * 2 + 1] + c.y;
                    *(float2*)(orow + col) = o;
                }
            }
        }
    }
}

// ---------------------------------------------------------------------------
extern "C" void kernel_launch(void* const* d_in, const int* in_sizes, int n_in,
                              void* d_out, int out_size) {
    const float* x     = (const float*)d_in[0];
    const int*   ei    = (const int*)  d_in[1];
    const float* eattr = (const float*)d_in[2];
    const float* u     = (const float*)d_in[3];
    const int*   batch = (const int*)  d_in[4];
    const float* WK    = (const float*)d_in[5];
    const float* bK    = (const float*)d_in[6];
    const float* WQ    = (const float*)d_in[7];
    const float* bQ    = (const float*)d_in[8];
    float* out = (float*)d_out;

    const int E = in_sizes[2];
    const int N = in_sizes[0] / FX;
    const int B = in_sizes[3] / FU;

    detect_kernel<<<1, 256>>>(ei, batch, E, N);

    long n4 = (long)N * FX / 4;
    zero_kernel<<<(unsigned)((n4 + 255) / 256), 256>>>(n4);

    long long sthreads = (long long)E * 16;
    scatter_kernel<<<(unsigned)((sthreads + 255) / 256), 256>>>(ei, eattr, x, E);

    dim3 gu((B + 7) / 8, 2);
    ugemm_kernel<<<gu, 128>>>(u, WK, bK, WQ, bQ, B);

    cudaFuncSetAttribute(gemm_tc_kernel,
                         cudaFuncAttributeMaxDynamicSharedMemorySize,
                         GEMM_SMEM_BYTES);
    dim3 g((N + 127) / 128, 2);
    gemm_tc_kernel<<<g, 256, GEMM_SMEM_BYTES>>>(batch, WK, WQ, out, N);
}